// round 1
// baseline (speedup 1.0000x reference)
#include <cuda_runtime.h>

#define BATCH 16
#define HDIM 512
#define WDIM 512
#define HW (HDIM * WDIM)
#define NCH 3
#define NTOT (BATCH * NCH * HW)
#define NLM 32          // 12 eye + 20 mouth landmarks per batch
#define BOX 29          // offsets -14..14 (dist < 15 support)
#define R2 225          // 15^2

// Scratch (device globals — no allocation allowed in kernel_launch)
__device__ unsigned int  g_eye  [BATCH * HW];   // float bits, atomicMax-able (values >= 0)
__device__ unsigned int  g_mouth[BATCH * HW];
__device__ unsigned char g_flag [BATCH * 32 * 32]; // 16x16-px coarse tiles
__device__ double        g_acc;

// ---------------------------------------------------------------------------
// Kernel 1: clear landmark boxes in mask buffers, clear tile flags + acc.
// ---------------------------------------------------------------------------
__global__ void clear_kernel(const int* __restrict__ lm) {
    int bid = blockIdx.x;
    if (bid == BATCH * NLM) {
        // clear flags (16 KB) with uint4 stores + clear accumulator
        uint4* f4 = reinterpret_cast<uint4*>(g_flag);
        for (int i = threadIdx.x; i < (BATCH * 32 * 32) / 16; i += blockDim.x)
            f4[i] = make_uint4(0u, 0u, 0u, 0u);
        if (threadIdx.x == 0) g_acc = 0.0;
        return;
    }
    int b = bid / NLM, l = bid % NLM;
    const int* p = lm + (b * 68 + 36 + l) * 2;   // eye slice 36..47, mouth 48..67
    int cx = min(max(p[0], 0), WDIM - 1);
    int cy = min(max(p[1], 0), HDIM - 1);
    unsigned int* buf = (l < 12) ? g_eye : g_mouth;
    for (int i = threadIdx.x; i < BOX * BOX; i += blockDim.x) {
        int dx = i % BOX - 14, dy = i / BOX - 14;
        int x = cx + dx, y = cy + dy;
        if (x < 0 || x >= WDIM || y < 0 || y >= HDIM) continue;
        buf[b * HW + y * WDIM + x] = 0u;
    }
}

// ---------------------------------------------------------------------------
// Kernel 2: splat radial kernels via atomicMax on float bits; mark hot tiles.
// ---------------------------------------------------------------------------
__global__ void splat_kernel(const int* __restrict__ lm) {
    int bid = blockIdx.x;
    int b = bid / NLM, l = bid % NLM;
    const int* p = lm + (b * 68 + 36 + l) * 2;
    int cx = min(max(p[0], 0), WDIM - 1);
    int cy = min(max(p[1], 0), HDIM - 1);
    unsigned int* buf = (l < 12) ? g_eye : g_mouth;

    if (threadIdx.x == 0) {
        int x0 = max(cx - 14, 0) >> 4, x1 = min(cx + 14, WDIM - 1) >> 4;
        int y0 = max(cy - 14, 0) >> 4, y1 = min(cy + 14, HDIM - 1) >> 4;
        for (int ty = y0; ty <= y1; ty++)
            for (int tx = x0; tx <= x1; tx++)
                g_flag[b * 1024 + ty * 32 + tx] = 1;
    }

    for (int i = threadIdx.x; i < BOX * BOX; i += blockDim.x) {
        int dx = i % BOX - 14, dy = i / BOX - 14;
        int x = cx + dx, y = cy + dy;
        if (x < 0 || x >= WDIM || y < 0 || y >= HDIM) continue;
        int d2 = dx * dx + dy * dy;
        if (d2 >= R2) continue;
        float val = 1.0f - sqrtf((float)d2) * (1.0f / 15.0f);
        atomicMax(&buf[b * HW + y * WDIM + x], __float_as_uint(val));
    }
}

// ---------------------------------------------------------------------------
// Kernel 3: main weighted-|diff| reduction. float4 over pixels, 3 channels.
// ---------------------------------------------------------------------------
__global__ void reduce_kernel(const float* __restrict__ pred,
                              const float* __restrict__ targ) {
    const int nq = BATCH * HW / 4;   // 1,048,576 pixel-quads
    float s = 0.0f;
    for (int q = blockIdx.x * blockDim.x + threadIdx.x; q < nq;
         q += gridDim.x * blockDim.x) {
        int b   = q >> 16;           // HW/4 = 65536
        int rem = q & 65535;
        int row = rem >> 7;          // 128 quads per row
        int x   = (rem & 127) << 2;
        int pidx = b * HW + row * WDIM + x;

        float w0 = 1.0f, w1 = 1.0f, w2 = 1.0f, w3 = 1.0f;
        unsigned char f = g_flag[(b << 10) + ((row >> 4) << 5) + (x >> 4)];
        if (f) {
            float4 e = *reinterpret_cast<const float4*>(&g_eye[pidx]);
            float4 m = *reinterpret_cast<const float4*>(&g_mouth[pidx]);
            w0 = 1.0f + 299.0f * fminf(e.x + m.x, 1.0f);
            w1 = 1.0f + 299.0f * fminf(e.y + m.y, 1.0f);
            w2 = 1.0f + 299.0f * fminf(e.z + m.z, 1.0f);
            w3 = 1.0f + 299.0f * fminf(e.w + m.w, 1.0f);
        }

        int base = b * NCH * HW + row * WDIM + x;
        #pragma unroll
        for (int c = 0; c < NCH; c++) {
            float4 p = *reinterpret_cast<const float4*>(pred + base + c * HW);
            float4 t = *reinterpret_cast<const float4*>(targ + base + c * HW);
            s += w0 * fabsf(p.x - t.x);
            s += w1 * fabsf(p.y - t.y);
            s += w2 * fabsf(p.z - t.z);
            s += w3 * fabsf(p.w - t.w);
        }
    }

    // warp reduce
    #pragma unroll
    for (int off = 16; off; off >>= 1)
        s += __shfl_down_sync(0xffffffffu, s, off);

    __shared__ float ws[8];
    int lane = threadIdx.x & 31, wid = threadIdx.x >> 5;
    if (lane == 0) ws[wid] = s;
    __syncthreads();
    if (wid == 0) {
        s = (lane < (int)(blockDim.x >> 5)) ? ws[lane] : 0.0f;
        #pragma unroll
        for (int off = 4; off; off >>= 1)
            s += __shfl_down_sync(0xffffffffu, s, off);
        if (lane == 0) atomicAdd(&g_acc, (double)s);
    }
}

// ---------------------------------------------------------------------------
// Kernel 4: finalize mean.
// ---------------------------------------------------------------------------
__global__ void finalize_kernel(float* __restrict__ out) {
    out[0] = (float)(g_acc * (1.0 / (double)NTOT));
}

extern "C" void kernel_launch(void* const* d_in, const int* in_sizes, int n_in,
                              void* d_out, int out_size) {
    const float* pred = (const float*)d_in[0];
    const float* targ = (const float*)d_in[1];
    const int*   lm   = (const int*)d_in[2];
    float*       out  = (float*)d_out;

    clear_kernel   <<<BATCH * NLM + 1, 256>>>(lm);
    splat_kernel   <<<BATCH * NLM,     256>>>(lm);
    reduce_kernel  <<<148 * 8,         256>>>(pred, targ);
    finalize_kernel<<<1, 1>>>(out);
}

// round 2
// speedup vs baseline: 1.1879x; 1.1879x over previous
#include <cuda_runtime.h>

#define BATCH 16
#define HDIM 512
#define WDIM 512
#define HW (HDIM * WDIM)
#define NTOT (BATCH * 3 * HW)
#define GRID (BATCH * 32)      // one block per (batch, 16-row strip)

__device__ double       g_acc;
__device__ unsigned int g_count;

__global__ void __launch_bounds__(256)
fused_loss_kernel(const float* __restrict__ pred,
                  const float* __restrict__ targ,
                  const int*   __restrict__ lm,
                  float*       __restrict__ out) {
    __shared__ float scx[32], scy[32];
    __shared__ int   s_iseye[32];
    __shared__ int   s_cnt;
    __shared__ float s_warp[8];

    const int bid   = blockIdx.x;
    const int b     = bid >> 5;
    const int strip = bid & 31;
    const int y0    = strip << 4;
    const int t     = threadIdx.x;

    if (t == 0) s_cnt = 0;
    __syncthreads();

    // Warp 0: filter this batch's 32 landmarks (36..67) by strip y-range.
    if (t < 32) {
        int cx = lm[(b * 68 + 36 + t) * 2 + 0];
        int cy = lm[(b * 68 + 36 + t) * 2 + 1];
        cx = min(max(cx, 0), WDIM - 1);
        cy = min(max(cy, 0), HDIM - 1);
        if (cy >= y0 - 15 && cy <= y0 + 30) {      // loose superset is safe
            int slot = atomicAdd(&s_cnt, 1);
            scx[slot]     = (float)cx;
            scy[slot]     = (float)cy;
            s_iseye[slot] = (t < 12);
        }
    }
    __syncthreads();
    const int cnt = s_cnt;

    // Thread -> one row of the strip; 8 quads per thread, 256B-coalesced.
    const int   r    = t >> 4;           // 0..15
    const int   y    = y0 + r;
    const float yf   = (float)y;
    const int   xq   = (t & 15) << 2;    // base x of first quad
    const int   base = b * 3 * HW + y * WDIM;

    float acc = 0.0f;

    #pragma unroll
    for (int k = 0; k < 8; k++) {
        const int   x  = xq + (k << 6);
        const float xf = (float)x;

        float e0 = 0.f, e1 = 0.f, e2 = 0.f, e3 = 0.f;
        float m0 = 0.f, m1 = 0.f, m2 = 0.f, m3 = 0.f;

        for (int j = 0; j < cnt; j++) {
            const float cx = scx[j], cy = scy[j];
            const float dy  = yf - cy;
            const float dy2 = dy * dy;
            // loose bb: pixels x..x+3, any within r<15 of cx
            if (dy2 < 225.f && fabsf(xf + 1.5f - cx) < 18.f) {
                const float dx0 = xf - cx;
                const float dx1 = dx0 + 1.f, dx2 = dx0 + 2.f, dx3 = dx0 + 3.f;
                const float v0 = 1.f - sqrtf(fmaf(dx0, dx0, dy2)) * (1.f / 15.f);
                const float v1 = 1.f - sqrtf(fmaf(dx1, dx1, dy2)) * (1.f / 15.f);
                const float v2 = 1.f - sqrtf(fmaf(dx2, dx2, dy2)) * (1.f / 15.f);
                const float v3 = 1.f - sqrtf(fmaf(dx3, dx3, dy2)) * (1.f / 15.f);
                if (s_iseye[j]) {   // uniform branch across block
                    e0 = fmaxf(e0, v0); e1 = fmaxf(e1, v1);
                    e2 = fmaxf(e2, v2); e3 = fmaxf(e3, v3);
                } else {
                    m0 = fmaxf(m0, v0); m1 = fmaxf(m1, v1);
                    m2 = fmaxf(m2, v2); m3 = fmaxf(m3, v3);
                }
            }
        }

        const float w0 = fmaf(fminf(e0 + m0, 1.f), 299.f, 1.f);
        const float w1 = fmaf(fminf(e1 + m1, 1.f), 299.f, 1.f);
        const float w2 = fmaf(fminf(e2 + m2, 1.f), 299.f, 1.f);
        const float w3 = fmaf(fminf(e3 + m3, 1.f), 299.f, 1.f);

        #pragma unroll
        for (int c = 0; c < 3; c++) {
            const float4 p  = *reinterpret_cast<const float4*>(pred + base + c * HW + x);
            const float4 tt = *reinterpret_cast<const float4*>(targ + base + c * HW + x);
            acc += w0 * fabsf(p.x - tt.x);
            acc += w1 * fabsf(p.y - tt.y);
            acc += w2 * fabsf(p.z - tt.z);
            acc += w3 * fabsf(p.w - tt.w);
        }
    }

    // Block reduction
    #pragma unroll
    for (int off = 16; off; off >>= 1)
        acc += __shfl_down_sync(0xffffffffu, acc, off);

    const int lane = t & 31, wid = t >> 5;
    if (lane == 0) s_warp[wid] = acc;
    __syncthreads();
    if (wid == 0) {
        acc = (lane < 8) ? s_warp[lane] : 0.0f;
        #pragma unroll
        for (int off = 4; off; off >>= 1)
            acc += __shfl_down_sync(0xffffffffu, acc, off);

        if (lane == 0) {
            atomicAdd(&g_acc, (double)acc);
            __threadfence();
            unsigned int ticket = atomicAdd(&g_count, 1u);
            if (ticket == GRID - 1) {
                __threadfence();
                double total = *((volatile double*)&g_acc);
                out[0] = (float)(total * (1.0 / (double)NTOT));
                g_acc   = 0.0;          // leave clean state for next replay
                g_count = 0u;
            }
        }
    }
}

extern "C" void kernel_launch(void* const* d_in, const int* in_sizes, int n_in,
                              void* d_out, int out_size) {
    const float* pred = (const float*)d_in[0];
    const float* targ = (const float*)d_in[1];
    const int*   lm   = (const int*)d_in[2];
    float*       out  = (float*)d_out;

    fused_loss_kernel<<<GRID, 256>>>(pred, targ, lm, out);
}

// round 3
// speedup vs baseline: 1.2922x; 1.0878x over previous
#include <cuda_runtime.h>

#define BATCH 16
#define HDIM 512
#define WDIM 512
#define HW (HDIM * WDIM)
#define NTOT (BATCH * 3 * HW)
#define STRIPS 128                 // per batch, 4 rows each
#define GRID (BATCH * STRIPS)      // 2048 blocks

__device__ double       g_acc;
__device__ unsigned int g_count;

__global__ void __launch_bounds__(256, 5)
fused_loss_kernel(const float* __restrict__ pred,
                  const float* __restrict__ targ,
                  const int*   __restrict__ lm,
                  float*       __restrict__ out) {
    __shared__ float scx[32], scy[32];
    __shared__ int   s_iseye[32];
    __shared__ int   s_cnt;
    __shared__ float s_warp[8];

    const int bid   = blockIdx.x;
    const int b     = bid >> 7;
    const int strip = bid & 127;
    const int y0    = strip << 2;          // 4-row strip
    const int t     = threadIdx.x;

    if (t == 0) s_cnt = 0;
    __syncthreads();

    // Filter this batch's 32 landmarks (indices 36..67) by strip y-range.
    if (t < 32) {
        int cx = lm[(b * 68 + 36 + t) * 2 + 0];
        int cy = lm[(b * 68 + 36 + t) * 2 + 1];
        cx = min(max(cx, 0), WDIM - 1);
        cy = min(max(cy, 0), HDIM - 1);
        if (cy >= y0 - 15 && cy <= y0 + 18) {          // loose superset
            int slot = atomicAdd(&s_cnt, 1);
            scx[slot]     = (float)cx;
            scy[slot]     = (float)cy;
            s_iseye[slot] = (t < 12);
        }
    }
    __syncthreads();
    const int cnt = s_cnt;

    // Thread -> (row, 2 quads). 64 threads per row, quads at x and x+256.
    const int   row  = t >> 6;             // 0..3
    const int   lane = t & 63;
    const int   y    = y0 + row;
    const float yf   = (float)y;
    const int   xb   = lane << 2;

    // ---- Phase 1: weights only (ALU, no global memory) ----
    float w[2][4];
    #pragma unroll
    for (int k = 0; k < 2; k++) {
        const int   x  = xb + (k << 8);
        const float xf = (float)x;
        float e0 = 0.f, e1 = 0.f, e2 = 0.f, e3 = 0.f;
        float m0 = 0.f, m1 = 0.f, m2 = 0.f, m3 = 0.f;
        for (int j = 0; j < cnt; j++) {
            const float cx = scx[j], cy = scy[j];
            const float dy  = yf - cy;
            const float dy2 = dy * dy;
            if (dy2 < 225.f && fabsf(xf + 1.5f - cx) < 18.f) {
                const float dx0 = xf - cx;
                const float dx1 = dx0 + 1.f, dx2 = dx0 + 2.f, dx3 = dx0 + 3.f;
                const float v0 = 1.f - sqrtf(fmaf(dx0, dx0, dy2)) * (1.f / 15.f);
                const float v1 = 1.f - sqrtf(fmaf(dx1, dx1, dy2)) * (1.f / 15.f);
                const float v2 = 1.f - sqrtf(fmaf(dx2, dx2, dy2)) * (1.f / 15.f);
                const float v3 = 1.f - sqrtf(fmaf(dx3, dx3, dy2)) * (1.f / 15.f);
                if (s_iseye[j]) {
                    e0 = fmaxf(e0, v0); e1 = fmaxf(e1, v1);
                    e2 = fmaxf(e2, v2); e3 = fmaxf(e3, v3);
                } else {
                    m0 = fmaxf(m0, v0); m1 = fmaxf(m1, v1);
                    m2 = fmaxf(m2, v2); m3 = fmaxf(m3, v3);
                }
            }
        }
        w[k][0] = fmaf(fminf(e0 + m0, 1.f), 299.f, 1.f);
        w[k][1] = fmaf(fminf(e1 + m1, 1.f), 299.f, 1.f);
        w[k][2] = fmaf(fminf(e2 + m2, 1.f), 299.f, 1.f);
        w[k][3] = fmaf(fminf(e3 + m3, 1.f), 299.f, 1.f);
    }

    // ---- Phase 2: 12 independent float4 load-pairs, straight-line ----
    const int base = b * 3 * HW + y * WDIM + xb;
    float acc = 0.0f;
    #pragma unroll
    for (int k = 0; k < 2; k++) {
        #pragma unroll
        for (int c = 0; c < 3; c++) {
            const int    off = c * HW + (k << 8);
            const float4 p   = *reinterpret_cast<const float4*>(pred + base + off);
            const float4 tt  = *reinterpret_cast<const float4*>(targ + base + off);
            acc += w[k][0] * fabsf(p.x - tt.x);
            acc += w[k][1] * fabsf(p.y - tt.y);
            acc += w[k][2] * fabsf(p.z - tt.z);
            acc += w[k][3] * fabsf(p.w - tt.w);
        }
    }

    // ---- Block reduction + device-side finalize ----
    #pragma unroll
    for (int off = 16; off; off >>= 1)
        acc += __shfl_down_sync(0xffffffffu, acc, off);

    const int lane32 = t & 31, wid = t >> 5;
    if (lane32 == 0) s_warp[wid] = acc;
    __syncthreads();
    if (wid == 0) {
        acc = (lane32 < 8) ? s_warp[lane32] : 0.0f;
        #pragma unroll
        for (int off = 4; off; off >>= 1)
            acc += __shfl_down_sync(0xffffffffu, acc, off);

        if (lane32 == 0) {
            atomicAdd(&g_acc, (double)acc);
            __threadfence();
            unsigned int ticket = atomicAdd(&g_count, 1u);
            if (ticket == GRID - 1) {
                __threadfence();
                double total = *((volatile double*)&g_acc);
                out[0] = (float)(total * (1.0 / (double)NTOT));
                g_acc   = 0.0;          // clean state for next graph replay
                g_count = 0u;
            }
        }
    }
}

extern "C" void kernel_launch(void* const* d_in, const int* in_sizes, int n_in,
                              void* d_out, int out_size) {
    const float* pred = (const float*)d_in[0];
    const float* targ = (const float*)d_in[1];
    const int*   lm   = (const int*)d_in[2];
    float*       out  = (float*)d_out;

    fused_loss_kernel<<<GRID, 256>>>(pred, targ, lm, out);
}